// round 1
// baseline (speedup 1.0000x reference)
#include <cuda_runtime.h>
#include <math.h>

// ---------------------------------------------------------------------------
// NonLinearConv2d: out = BN( R_TIA * ALPHA * sum_k [ sp(z)^2 - sp(z-4/3)^2 ] )
//   z = (V - theta)/0.075,  sp = softplus, BN = training-mode batchnorm
// Strategy: 2048-segment piecewise-linear table of
//   g(z) = sp(z)^2 - sp(z - 4/3)^2  over z in [-13, 15]
// stored as (intercept, slope) in t-space where t = (z + 13) * (2048/28).
// Segment 0 is exactly (0,0) (g < 1e-11 below -13); segment 2047 is the exact
// asymptote g = (8/3)z - 16/9 (error < 3e-5 above 15). Index is clamped but
// evaluation uses the UNCLAMPED t, so both edges extrapolate exactly.
// ---------------------------------------------------------------------------

#define NTAB 2048

static __device__ float2 g_tab[NTAB];      // (at, bt): g = at + bt * t
static __device__ float  g_nthh[27 * 64];  // (-theta/0.075 + 13) * (2048/28)

__device__ __forceinline__ double sp_d(double z) {
    return z > 0.0 ? z + log1p(exp(-z)) : log1p(exp(z));
}

__global__ void init_kernel(const float* __restrict__ theta) {
    int i = blockIdx.x * blockDim.x + threadIdx.x;
    const double H     = 28.0 / 2048.0;
    const double ZLO   = -13.0;
    const double SHIFT = 0.1 / 0.075;  // 4/3
    if (i < NTAB) {
        double a, b;
        if (i == 0) {
            a = 0.0; b = 0.0;                       // dead zone
        } else if (i == NTAB - 1) {
            b = 8.0 / 3.0; a = -16.0 / 9.0;         // exact asymptote
        } else {
            double z0 = ZLO + i * H, z1 = z0 + H;
            double s00 = sp_d(z0), s01 = sp_d(z0 - SHIFT);
            double s10 = sp_d(z1), s11 = sp_d(z1 - SHIFT);
            double g0 = s00 * s00 - s01 * s01;
            double g1 = s10 * s10 - s11 * s11;
            b = (g1 - g0) / H;
            a = g0 - b * z0;
        }
        // convert to t-space: z = ZLO + t*H  =>  g = (a + b*ZLO) + (b*H)*t
        g_tab[i] = make_float2((float)(a + b * ZLO), (float)(b * H));
    }
    if (i < 27 * 64) {
        const double INV_D = 1.0 / 0.075;
        const double INV_H = 2048.0 / 28.0;
        g_nthh[i] = (float)(((-(double)theta[i]) * INV_D + 13.0) * INV_H);
    }
}

// ---------------------------------------------------------------------------
// Main compute: thread = (pixel within 64-pixel tile, channel-group of 16).
// Warp = 32 consecutive pixels, same channel group -> theta broadcast in LDS,
// coalesced x loads, coalesced per-channel output stores.
// ---------------------------------------------------------------------------
__global__ __launch_bounds__(256)
void conv_kernel(const float* __restrict__ x, float* __restrict__ out) {
    __shared__ float2 tab_s[NTAB];          // 16 KB
    __shared__ float  nthh_s[27][64];       // 6.75 KB

    for (int i = threadIdx.x; i < NTAB; i += 256) tab_s[i] = g_tab[i];
    for (int i = threadIdx.x; i < 27 * 64; i += 256) (&nthh_s[0][0])[i] = g_nthh[i];
    __syncthreads();

    const float INV_DH = (float)((1.0 / 0.075) * (2048.0 / 28.0)); // 975.238...

    int tid = threadIdx.x;
    int pix = tid & 63;        // 0..63 pixel within block tile
    int cg  = tid >> 6;        // 0..3 channel group
    int gp  = blockIdx.x * 64 + pix;   // global pixel id over N*L = 32768
    int n   = gp >> 10;
    int l   = gp & 1023;
    int hh  = l >> 5, ww = l & 31;
    const float* xb = x + n * 3072;    // 3*32*32 per image
    int c0 = cg * 16;

    float acc[16];
#pragma unroll
    for (int c = 0; c < 16; c++) acc[c] = 0.0f;

#pragma unroll 1
    for (int ci = 0; ci < 3; ci++) {
#pragma unroll 1
        for (int ki = 0; ki < 3; ki++) {
            int hy = hh + ki - 1;
            bool rowok = (unsigned)hy < 32u;
            const float* row = xb + ci * 1024 + hy * 32;
            int kb = ci * 9 + ki * 3;
#pragma unroll
            for (int kj = 0; kj < 3; kj++) {
                int wx = ww + kj - 1;
                float V = (rowok && (unsigned)wx < 32u) ? __ldg(row + wx) : 0.0f;
                float u = V * INV_DH;
                const float* nt = &nthh_s[kb + kj][c0];
#pragma unroll
                for (int c = 0; c < 16; c++) {
                    float t  = u + nt[c];                       // t-index, linear in z
                    float tc = fminf(fmaxf(t, 0.0f), 2047.0f);  // clamp index only
                    float2 ab = tab_s[(int)tc];
                    acc[c] = fmaf(ab.y, t, acc[c] + ab.x);      // g = at + bt*t
                }
            }
        }
    }

    const float SCALE = 0.0005625f * 0.1f;  // ALPHA * R_TIA
    float* o = out + (n * 64 + c0) * 1024 + l;
#pragma unroll
    for (int c = 0; c < 16; c++) o[c * 1024] = acc[c] * SCALE;
}

// ---------------------------------------------------------------------------
// BatchNorm (training mode, biased var): one block per channel.
// Pass 1: sum & sumsq over 32*1024 elements; pass 2: normalize in place.
// Data stays L2-hot between passes (8 MB total).
// ---------------------------------------------------------------------------
__global__ __launch_bounds__(512)
void bn_kernel(float* __restrict__ out,
               const float* __restrict__ gamma,
               const float* __restrict__ beta) {
    int c = blockIdx.x;       // 0..63
    int tid = threadIdx.x;    // 0..511
    float s = 0.0f, s2 = 0.0f;
    for (int i = tid; i < 32768; i += 512) {
        int nn = i >> 10, ll = i & 1023;
        float v = out[(nn * 64 + c) * 1024 + ll];
        s += v;
        s2 = fmaf(v, v, s2);
    }
    __shared__ float ss[512], ss2[512];
    ss[tid] = s; ss2[tid] = s2;
    __syncthreads();
    for (int off = 256; off > 0; off >>= 1) {
        if (tid < off) { ss[tid] += ss[tid + off]; ss2[tid] += ss2[tid + off]; }
        __syncthreads();
    }
    __shared__ float sc_s, bi_s;
    if (tid == 0) {
        const float invN = 1.0f / 32768.0f;
        float mean = ss[0] * invN;
        float var  = ss2[0] * invN - mean * mean;
        float sc   = gamma[c] * rsqrtf(var + 1e-5f);
        sc_s = sc;
        bi_s = beta[c] - mean * sc;
    }
    __syncthreads();
    float sc = sc_s, bi = bi_s;
    for (int i = tid; i < 32768; i += 512) {
        int nn = i >> 10, ll = i & 1023;
        int idx = (nn * 64 + c) * 1024 + ll;
        out[idx] = fmaf(out[idx], sc, bi);
    }
}

// ---------------------------------------------------------------------------
extern "C" void kernel_launch(void* const* d_in, const int* in_sizes, int n_in,
                              void* d_out, int out_size) {
    const float* x     = (const float*)d_in[0];  // (32,3,32,32)
    const float* theta = (const float*)d_in[1];  // (27,64)
    const float* gamma = (const float*)d_in[2];  // (64)
    const float* beta  = (const float*)d_in[3];  // (64)
    float* out = (float*)d_out;                  // (32,64,32,32)

    init_kernel<<<8, 256>>>(theta);              // table + theta preprocessing
    conv_kernel<<<512, 256>>>(x, out);           // 32768 pixels / 64 per block
    bn_kernel<<<64, 512>>>(out, gamma, beta);    // one block per channel
}

// round 2
// speedup vs baseline: 1.0213x; 1.0213x over previous
#include <cuda_runtime.h>
#include <math.h>

// ---------------------------------------------------------------------------
// NonLinearConv2d: out = BN( R_TIA * ALPHA * sum_k [ sp(z)^2 - sp(z-4/3)^2 ] )
//   z = (V - theta)/0.075,  sp = softplus, BN = training-mode batchnorm
// Strategy: 2048-segment piecewise-linear table of
//   g(z) = sp(z)^2 - sp(z - 4/3)^2  over z in [-13, 15]
// stored as (intercept, slope) in t-space where t = (z + 13) * (2048/28).
// Segment 0 is exactly (0,0) (g < 1e-11 below -13); segment 2047 is the exact
// asymptote g = (8/3)z - 16/9 (error < 3e-5 above 15). Index is clamped but
// evaluation uses the UNCLAMPED t, so both edges extrapolate exactly.
// ---------------------------------------------------------------------------

#define NTAB 2048

static __device__ float2 g_tab[NTAB];      // (at, bt): g = at + bt * t
static __device__ float  g_nthh[27 * 64];  // (-theta/0.075 + 13) * (2048/28)

__device__ __forceinline__ double sp_d(double z) {
    return z > 0.0 ? z + log1p(exp(-z)) : log1p(exp(z));
}

__global__ void init_kernel(const float* __restrict__ theta) {
    int i = blockIdx.x * blockDim.x + threadIdx.x;
    const double H     = 28.0 / 2048.0;
    const double ZLO   = -13.0;
    const double SHIFT = 0.1 / 0.075;  // 4/3
    if (i < NTAB) {
        double a, b;
        if (i == 0) {
            a = 0.0; b = 0.0;                       // dead zone
        } else if (i == NTAB - 1) {
            b = 8.0 / 3.0; a = -16.0 / 9.0;         // exact asymptote
        } else {
            double z0 = ZLO + i * H, z1 = z0 + H;
            double s00 = sp_d(z0), s01 = sp_d(z0 - SHIFT);
            double s10 = sp_d(z1), s11 = sp_d(z1 - SHIFT);
            double g0 = s00 * s00 - s01 * s01;
            double g1 = s10 * s10 - s11 * s11;
            b = (g1 - g0) / H;
            a = g0 - b * z0;
        }
        // convert to t-space: z = ZLO + t*H  =>  g = (a + b*ZLO) + (b*H)*t
        g_tab[i] = make_float2((float)(a + b * ZLO), (float)(b * H));
    }
    if (i < 27 * 64) {
        const double INV_D = 1.0 / 0.075;
        const double INV_H = 2048.0 / 28.0;
        g_nthh[i] = (float)(((-(double)theta[i]) * INV_D + 13.0) * INV_H);
    }
}

// ---------------------------------------------------------------------------
// Main compute: thread = (pixel within 64-pixel tile, channel-group of 16).
// Warp = 32 consecutive pixels, same channel group -> theta broadcast in LDS,
// coalesced x loads, coalesced per-channel output stores.
// ---------------------------------------------------------------------------
__global__ __launch_bounds__(256)
void conv_kernel(const float* __restrict__ x, float* __restrict__ out) {
    __shared__ float2 tab_s[NTAB];          // 16 KB
    __shared__ float  nthh_s[27][64];       // 6.75 KB

    for (int i = threadIdx.x; i < NTAB; i += 256) tab_s[i] = g_tab[i];
    for (int i = threadIdx.x; i < 27 * 64; i += 256) (&nthh_s[0][0])[i] = g_nthh[i];
    __syncthreads();

    const float INV_DH = (float)((1.0 / 0.075) * (2048.0 / 28.0)); // 975.238...

    int tid = threadIdx.x;
    int pix = tid & 63;        // 0..63 pixel within block tile
    int cg  = tid >> 6;        // 0..3 channel group
    int gp  = blockIdx.x * 64 + pix;   // global pixel id over N*L = 32768
    int n   = gp >> 10;
    int l   = gp & 1023;
    int hh  = l >> 5, ww = l & 31;
    const float* xb = x + n * 3072;    // 3*32*32 per image
    int c0 = cg * 16;

    float acc[16];
#pragma unroll
    for (int c = 0; c < 16; c++) acc[c] = 0.0f;

#pragma unroll 1
    for (int ci = 0; ci < 3; ci++) {
#pragma unroll 1
        for (int ki = 0; ki < 3; ki++) {
            int hy = hh + ki - 1;
            bool rowok = (unsigned)hy < 32u;
            const float* row = xb + ci * 1024 + hy * 32;
            int kb = ci * 9 + ki * 3;
#pragma unroll
            for (int kj = 0; kj < 3; kj++) {
                int wx = ww + kj - 1;
                float V = (rowok && (unsigned)wx < 32u) ? __ldg(row + wx) : 0.0f;
                float u = V * INV_DH;
                const float* nt = &nthh_s[kb + kj][c0];
#pragma unroll
                for (int c = 0; c < 16; c++) {
                    float t  = u + nt[c];                       // t-index, linear in z
                    float tc = fminf(fmaxf(t, 0.0f), 2047.0f);  // clamp index only
                    float2 ab = tab_s[(int)tc];
                    acc[c] = fmaf(ab.y, t, acc[c] + ab.x);      // g = at + bt*t
                }
            }
        }
    }

    const float SCALE = 0.0005625f * 0.1f;  // ALPHA * R_TIA
    float* o = out + (n * 64 + c0) * 1024 + l;
#pragma unroll
    for (int c = 0; c < 16; c++) o[c * 1024] = acc[c] * SCALE;
}

// ---------------------------------------------------------------------------
// BatchNorm (training mode, biased var): one block per channel.
// Pass 1: sum & sumsq over 32*1024 elements; pass 2: normalize in place.
// Data stays L2-hot between passes (8 MB total).
// ---------------------------------------------------------------------------
__global__ __launch_bounds__(512)
void bn_kernel(float* __restrict__ out,
               const float* __restrict__ gamma,
               const float* __restrict__ beta) {
    int c = blockIdx.x;       // 0..63
    int tid = threadIdx.x;    // 0..511
    float s = 0.0f, s2 = 0.0f;
    for (int i = tid; i < 32768; i += 512) {
        int nn = i >> 10, ll = i & 1023;
        float v = out[(nn * 64 + c) * 1024 + ll];
        s += v;
        s2 = fmaf(v, v, s2);
    }
    __shared__ float ss[512], ss2[512];
    ss[tid] = s; ss2[tid] = s2;
    __syncthreads();
    for (int off = 256; off > 0; off >>= 1) {
        if (tid < off) { ss[tid] += ss[tid + off]; ss2[tid] += ss2[tid + off]; }
        __syncthreads();
    }
    __shared__ float sc_s, bi_s;
    if (tid == 0) {
        const float invN = 1.0f / 32768.0f;
        float mean = ss[0] * invN;
        float var  = ss2[0] * invN - mean * mean;
        float sc   = gamma[c] * rsqrtf(var + 1e-5f);
        sc_s = sc;
        bi_s = beta[c] - mean * sc;
    }
    __syncthreads();
    float sc = sc_s, bi = bi_s;
    for (int i = tid; i < 32768; i += 512) {
        int nn = i >> 10, ll = i & 1023;
        int idx = (nn * 64 + c) * 1024 + ll;
        out[idx] = fmaf(out[idx], sc, bi);
    }
}

// ---------------------------------------------------------------------------
extern "C" void kernel_launch(void* const* d_in, const int* in_sizes, int n_in,
                              void* d_out, int out_size) {
    const float* x     = (const float*)d_in[0];  // (32,3,32,32)
    const float* theta = (const float*)d_in[1];  // (27,64)
    const float* gamma = (const float*)d_in[2];  // (64)
    const float* beta  = (const float*)d_in[3];  // (64)
    float* out = (float*)d_out;                  // (32,64,32,32)

    init_kernel<<<8, 256>>>(theta);              // table + theta preprocessing
    conv_kernel<<<512, 256>>>(x, out);           // 32768 pixels / 64 per block
    bn_kernel<<<64, 512>>>(out, gamma, beta);    // one block per channel
}